// round 12
// baseline (speedup 1.0000x reference)
#include <cuda_runtime.h>
#include <cuda_bf16.h>
#include <math.h>
#include <stdint.h>

// Problem constants
#define BB 32
#define TT 512
#define DD 512
#define UU 1024
#define NC 4096   // 4*U packed gate columns, layout [unit][gate], gate order f,i,g,o

#define NCTA 128      // persistent CTAs (1 per SM)
#define RPITCH 1048   // smem weight row pitch in bf16 elems (bank-conflict-free)
#define NWARP 16      // warps in persistent kernel
#define KWS 64        // K-slice per warp (1024/16)

// -------- device scratch --------
__device__ float g_bp[4096];                  // packed biases
__device__ float g_zx[(size_t)TT * BB * NC];  // [t][b][u*4+g]  x-part (+bias)
__device__ unsigned g_bar;                    // grid barrier counter
// bf16 hi/lo for tensor-core zx
__device__ __nv_bfloat16 g_xhi[(size_t)TT * BB * DD];  // [row=t*32+b][d]
__device__ __nv_bfloat16 g_xlo[(size_t)TT * BB * DD];
__device__ __nv_bfloat16 g_bwhi[(size_t)NC * DD];      // input W  [c][d]
__device__ __nv_bfloat16 g_bwlo[(size_t)NC * DD];
// bf16 hi/lo recurrent weights [c][k]
__device__ __nv_bfloat16 g_rwhi[(size_t)NC * UU];
__device__ __nv_bfloat16 g_rwlo[(size_t)NC * UU];
// bf16 hi/lo hidden state, ping-pong, layout [b][u-swizzled]
__device__ __nv_bfloat16 g_hhi[2][BB * UU];
__device__ __nv_bfloat16 g_hlo[2][BB * UU];

__device__ __forceinline__ float sigmoidf_(float x) {
    return 1.0f / (1.0f + __expf(-x));
}
__device__ __forceinline__ float tanhf_(float x) {
    return 1.0f - 2.0f / (__expf(2.0f * x) + 1.0f);
}

// -------- barrier primitives --------
__device__ __forceinline__ void bar_arrive_release(unsigned* p) {
    unsigned old;
    asm volatile("atom.add.release.gpu.u32 %0, [%1], 1;" : "=r"(old) : "l"(p) : "memory");
}
__device__ __forceinline__ unsigned ld_acquire(unsigned* p) {
    unsigned v;
    asm volatile("ld.acquire.gpu.u32 %0, [%1];" : "=r"(v) : "l"(p) : "memory");
    return v;
}

// -------- mma.sync bf16 --------
__device__ __forceinline__ void mma16816(float* c, const uint32_t* a, const uint32_t* b) {
    asm volatile(
        "mma.sync.aligned.m16n8k16.row.col.f32.bf16.bf16.f32 "
        "{%0,%1,%2,%3}, {%4,%5,%6,%7}, {%8,%9}, {%0,%1,%2,%3};"
        : "+f"(c[0]), "+f"(c[1]), "+f"(c[2]), "+f"(c[3])
        : "r"(a[0]), "r"(a[1]), "r"(a[2]), "r"(a[3]), "r"(b[0]), "r"(b[1]));
}

// fragment-swizzle: value index i (0..15) -> storage position within 16-tile
__device__ __forceinline__ int fragpos(int i) {
    return (i & 1) + ((i >> 3) << 1) + (i & 6) * 2;
}

// ===========================================================================
// Prep: biases, bf16 hi/lo input + recurrent weights, zero h0 + bar
// ===========================================================================
__global__ void prep_kernel(const float* __restrict__ Wf, const float* __restrict__ Wi,
                            const float* __restrict__ Wc, const float* __restrict__ Wo,
                            const float* __restrict__ bf, const float* __restrict__ bi,
                            const float* __restrict__ bc, const float* __restrict__ bo) {
    int idx = blockIdx.x * blockDim.x + threadIdx.x;
    int stride = gridDim.x * blockDim.x;
    if (idx == 0) g_bar = 0u;
    const float* Ws[4] = {Wf, Wi, Wc, Wo};

    for (int i = idx; i < 512 * 1024; i += stride) {
        int d = i >> 10, u = i & 1023;
        int s = (1024 + d) * 1024 + u;
#pragma unroll
        for (int g = 0; g < 4; g++) {
            float v = Ws[g][s];
            int c = u * 4 + g;
            __nv_bfloat16 h = __float2bfloat16(v);
            g_bwhi[(size_t)c * 512 + d] = h;
            g_bwlo[(size_t)c * 512 + d] = __float2bfloat16(v - __bfloat162float(h));
        }
    }
    for (size_t i = idx; i < (size_t)NC * UU; i += stride) {
        int c = (int)(i >> 10), k = (int)(i & 1023);
        int u = c >> 2, g = c & 3;
        float v = Ws[g][(size_t)k * 1024 + u];
        __nv_bfloat16 h = __float2bfloat16(v);
        g_rwhi[i] = h;
        g_rwlo[i] = __float2bfloat16(v - __bfloat162float(h));
    }
    for (int u = idx; u < 1024; u += stride)
        *(float4*)&g_bp[u << 2] = make_float4(bf[u], bi[u], bc[u], bo[u]);
    for (int i = idx; i < BB * UU; i += stride) {
        g_hhi[0][i] = __float2bfloat16(0.0f);
        g_hlo[0][i] = __float2bfloat16(0.0f);
    }
}

// ===========================================================================
// Convert x -> bf16 hi/lo, layout [row=t*32+b][d]
// ===========================================================================
__global__ void conv_x_kernel(const float* __restrict__ x) {
    int idx = blockIdx.x * blockDim.x + threadIdx.x;
    int stride = gridDim.x * blockDim.x;
    const int N4 = BB * TT * DD / 4;
    for (int i = idx; i < N4; i += stride) {
        int d4 = i & 127;
        int rt = i >> 7;           // b*512 + t
        int b = rt >> 9, t = rt & 511;
        float4 v = *(const float4*)&x[(size_t)i * 4];
        size_t o = ((size_t)(t * 32 + b)) * 512 + d4 * 4;

        __nv_bfloat16 h0 = __float2bfloat16(v.x);
        __nv_bfloat16 h1 = __float2bfloat16(v.y);
        __nv_bfloat16 h2 = __float2bfloat16(v.z);
        __nv_bfloat16 h3 = __float2bfloat16(v.w);
        __nv_bfloat162 hp0; hp0.x = h0; hp0.y = h1;
        __nv_bfloat162 hp1; hp1.x = h2; hp1.y = h3;
        *(__nv_bfloat162*)(g_xhi + o) = hp0;
        *(__nv_bfloat162*)(g_xhi + o + 2) = hp1;

        __nv_bfloat162 lp0, lp1;
        lp0.x = __float2bfloat16(v.x - __bfloat162float(h0));
        lp0.y = __float2bfloat16(v.y - __bfloat162float(h1));
        lp1.x = __float2bfloat16(v.z - __bfloat162float(h2));
        lp1.y = __float2bfloat16(v.w - __bfloat162float(h3));
        *(__nv_bfloat162*)(g_xlo + o) = lp0;
        *(__nv_bfloat162*)(g_xlo + o + 2) = lp1;
    }
}

// ===========================================================================
// zx GEMM via mma.sync (unchanged from R10/R11 win)
// ===========================================================================
#define ZMT 128
#define ZNT 64
#define ZKC 32
#define ZST 40

__global__ __launch_bounds__(256) void zx_mma_kernel() {
    __shared__ __align__(16) __nv_bfloat16 sAhi[ZMT * ZST];
    __shared__ __align__(16) __nv_bfloat16 sAlo[ZMT * ZST];
    __shared__ __align__(16) __nv_bfloat16 sBhi[ZNT * ZST];
    __shared__ __align__(16) __nv_bfloat16 sBlo[ZNT * ZST];

    const int tid = threadIdx.x;
    const int lane = tid & 31;
    const int wid = tid >> 5;
    const int wm = wid >> 1;
    const int wn = wid & 1;
    const int gr = lane >> 2;
    const int tg = lane & 3;
    const int n0 = blockIdx.x * ZNT;
    const int row0 = blockIdx.y * ZMT;

    float c[2][4][4];
#pragma unroll
    for (int mi = 0; mi < 2; mi++)
#pragma unroll
        for (int ni = 0; ni < 4; ni++)
#pragma unroll
            for (int r = 0; r < 4; r++) c[mi][ni][r] = 0.0f;

    for (int kc = 0; kc < DD / ZKC; kc++) {
        __syncthreads();
#pragma unroll
        for (int it = 0; it < 2; it++) {
            int idx = tid + it * 256;
            int r = idx >> 2, q = idx & 3;
            size_t go = ((size_t)(row0 + r)) * 512 + kc * 32 + q * 8;
            *(uint4*)&sAhi[r * ZST + q * 8] = *(const uint4*)(g_xhi + go);
            *(uint4*)&sAlo[r * ZST + q * 8] = *(const uint4*)(g_xlo + go);
        }
        {
            int r = tid >> 2, q = tid & 3;
            size_t go = ((size_t)(n0 + r)) * 512 + kc * 32 + q * 8;
            *(uint4*)&sBhi[r * ZST + q * 8] = *(const uint4*)(g_bwhi + go);
            *(uint4*)&sBlo[r * ZST + q * 8] = *(const uint4*)(g_bwlo + go);
        }
        __syncthreads();

#pragma unroll
        for (int ks = 0; ks < 2; ks++) {
            uint32_t ahi[2][4], alo[2][4];
#pragma unroll
            for (int mi = 0; mi < 2; mi++) {
                int rb = (wm * 32 + mi * 16 + gr) * ZST + ks * 16 + tg * 2;
                ahi[mi][0] = *(const uint32_t*)&sAhi[rb];
                ahi[mi][1] = *(const uint32_t*)&sAhi[rb + 8 * ZST];
                ahi[mi][2] = *(const uint32_t*)&sAhi[rb + 8];
                ahi[mi][3] = *(const uint32_t*)&sAhi[rb + 8 * ZST + 8];
                alo[mi][0] = *(const uint32_t*)&sAlo[rb];
                alo[mi][1] = *(const uint32_t*)&sAlo[rb + 8 * ZST];
                alo[mi][2] = *(const uint32_t*)&sAlo[rb + 8];
                alo[mi][3] = *(const uint32_t*)&sAlo[rb + 8 * ZST + 8];
            }
            uint32_t bhi[4][2], blo[4][2];
#pragma unroll
            for (int ni = 0; ni < 4; ni++) {
                int rb = (wn * 32 + ni * 8 + gr) * ZST + ks * 16 + tg * 2;
                bhi[ni][0] = *(const uint32_t*)&sBhi[rb];
                bhi[ni][1] = *(const uint32_t*)&sBhi[rb + 8];
                blo[ni][0] = *(const uint32_t*)&sBlo[rb];
                blo[ni][1] = *(const uint32_t*)&sBlo[rb + 8];
            }
#pragma unroll
            for (int mi = 0; mi < 2; mi++)
#pragma unroll
                for (int ni = 0; ni < 4; ni++) {
                    mma16816(c[mi][ni], ahi[mi], bhi[ni]);
                    mma16816(c[mi][ni], ahi[mi], blo[ni]);
                    mma16816(c[mi][ni], alo[mi], bhi[ni]);
                }
        }
    }

    const int rbase = row0 + wm * 32;
    const int cbase = n0 + wn * 32;
#pragma unroll
    for (int mi = 0; mi < 2; mi++) {
#pragma unroll
        for (int ni = 0; ni < 4; ni++) {
            int r = rbase + mi * 16 + gr;
            int col = cbase + ni * 8 + tg * 2;
            float2 b01 = *(const float2*)&g_bp[col];
            float2 v0 = make_float2(c[mi][ni][0] + b01.x, c[mi][ni][1] + b01.y);
            float2 v1 = make_float2(c[mi][ni][2] + b01.x, c[mi][ni][3] + b01.y);
            *(float2*)&g_zx[(size_t)r * NC + col] = v0;
            *(float2*)&g_zx[(size_t)(r + 8) * NC + col] = v1;
        }
    }
}

// ===========================================================================
// Persistent recurrent kernel via mma.sync (bf16x3), 512 threads / 16 warps.
// CTA cu owns 32 gate-cols (8 units). Weights resident in smem bf16 hi/lo.
// 16 warps K-split x64: warp does M32 x N32 x K64 = 4 k16 x (2m x 4n) x 3 mma.
// smem: weights 134144B + red[16][32][40] fp32 81920B = 216064B
// ===========================================================================
__global__ __launch_bounds__(512, 1) void lstm_persistent(float* __restrict__ out) {
    extern __shared__ __align__(16) char smem[];
    __nv_bfloat16* wshi = (__nv_bfloat16*)smem;          // [32][RPITCH]
    __nv_bfloat16* wslo = wshi + 32 * RPITCH;
    float* red = (float*)(smem + (size_t)32 * RPITCH * 2 * 2);  // [16][32][40]

    const int tid = threadIdx.x;
    const int cu = blockIdx.x;
    const int lane = tid & 31;
    const int wid = tid >> 5;       // 0..15
    const int gr = lane >> 2;
    const int tg = lane & 3;
    const int kb = wid * KWS;       // warp K-slice base

    // --- load resident weights ---
    for (int i = tid; i < 32 * 128; i += 512) {
        int lr = i >> 7, q = i & 127;
        size_t go = ((size_t)(cu * 32 + lr)) * 1024 + q * 8;
        *(uint4*)(wshi + lr * RPITCH + q * 8) = *(const uint4*)(g_rwhi + go);
        *(uint4*)(wslo + lr * RPITCH + q * 8) = *(const uint4*)(g_rwlo + go);
    }

    // --- gate-math roles (threads 0..255) ---
    const int up = (tid >> 5) & 7;  // unit-in-CTA 0..7 (valid for tid<256)
    const int gb = tid & 31;        // batch 0..31
    const int ug = cu * 8 + up;     // global unit
    const int i16 = ug & 15;
    const int hidx = (ug & ~15) + fragpos(i16);

    float c_state = 0.0f;
    __syncthreads();                // weights ready

    for (int t = 0; t < TT; t++) {
        const __nv_bfloat16* __restrict__ hhi = g_hhi[t & 1];
        const __nv_bfloat16* __restrict__ hlo = g_hlo[t & 1];
        __nv_bfloat16* __restrict__ hhio = g_hhi[(t + 1) & 1];
        __nv_bfloat16* __restrict__ hloo = g_hlo[(t + 1) & 1];

        float4 zx4 = make_float4(0.f, 0.f, 0.f, 0.f);
        if (tid < 256)
            zx4 = __ldcg((const float4*)&g_zx[((size_t)t * BB + gb) * NC + ug * 4]);

        float acc[2][4][4];
#pragma unroll
        for (int mi = 0; mi < 2; mi++)
#pragma unroll
            for (int ni = 0; ni < 4; ni++)
#pragma unroll
                for (int r = 0; r < 4; r++) acc[mi][ni][r] = 0.0f;

#define LDA(dst, u0) do { \
        (dst)[0] = __ldcg((const uint2*)(hhi + (gr)      * 1024 + (u0)) + tg); \
        (dst)[1] = __ldcg((const uint2*)(hhi + (gr + 8)  * 1024 + (u0)) + tg); \
        (dst)[2] = __ldcg((const uint2*)(hhi + (gr + 16) * 1024 + (u0)) + tg); \
        (dst)[3] = __ldcg((const uint2*)(hhi + (gr + 24) * 1024 + (u0)) + tg); \
        (dst)[4] = __ldcg((const uint2*)(hlo + (gr)      * 1024 + (u0)) + tg); \
        (dst)[5] = __ldcg((const uint2*)(hlo + (gr + 8)  * 1024 + (u0)) + tg); \
        (dst)[6] = __ldcg((const uint2*)(hlo + (gr + 16) * 1024 + (u0)) + tg); \
        (dst)[7] = __ldcg((const uint2*)(hlo + (gr + 24) * 1024 + (u0)) + tg); \
    } while (0)

#define COMPUTE(buf, k0) do { \
        uint32_t ah0[4] = {(buf)[0].x, (buf)[1].x, (buf)[0].y, (buf)[1].y}; \
        uint32_t ah1[4] = {(buf)[2].x, (buf)[3].x, (buf)[2].y, (buf)[3].y}; \
        uint32_t al0[4] = {(buf)[4].x, (buf)[5].x, (buf)[4].y, (buf)[5].y}; \
        uint32_t al1[4] = {(buf)[6].x, (buf)[7].x, (buf)[6].y, (buf)[7].y}; \
        _Pragma("unroll") \
        for (int ni = 0; ni < 4; ni++) { \
            const __nv_bfloat16* bh = wshi + (ni * 8 + gr) * RPITCH + (k0) + tg * 2; \
            const __nv_bfloat16* bl = wslo + (ni * 8 + gr) * RPITCH + (k0) + tg * 2; \
            uint32_t bhiv[2] = {*(const uint32_t*)bh, *(const uint32_t*)(bh + 8)}; \
            uint32_t blov[2] = {*(const uint32_t*)bl, *(const uint32_t*)(bl + 8)}; \
            mma16816(acc[0][ni], ah0, bhiv); \
            mma16816(acc[0][ni], ah0, blov); \
            mma16816(acc[0][ni], al0, bhiv); \
            mma16816(acc[1][ni], ah1, bhiv); \
            mma16816(acc[1][ni], ah1, blov); \
            mma16816(acc[1][ni], al1, bhiv); \
        } \
    } while (0)

        uint2 cur[8], nxt[8];
        LDA(cur, kb);
        LDA(nxt, kb + 16);
        COMPUTE(cur, kb);
        LDA(cur, kb + 32);
        COMPUTE(nxt, kb + 16);
        LDA(nxt, kb + 48);
        COMPUTE(cur, kb + 32);
        COMPUTE(nxt, kb + 48);

        // ---- write partials: red[wid][b][40] ----
#pragma unroll
        for (int mi = 0; mi < 2; mi++)
#pragma unroll
            for (int ni = 0; ni < 4; ni++) {
                float* b0 = &red[((size_t)wid * 32 + mi * 16 + gr) * 40 + ni * 8 + tg * 2];
                *(float2*)b0 = make_float2(acc[mi][ni][0], acc[mi][ni][1]);
                *(float2*)(b0 + 8 * 40) = make_float2(acc[mi][ni][2], acc[mi][ni][3]);
            }
        __syncthreads();

        // ---- reduce + gate math: thread = (unit up, batch gb), tid<256 ----
        float h_new = 0.0f;
        if (tid < 256) {
            float4 z = make_float4(0.f, 0.f, 0.f, 0.f);
#pragma unroll
            for (int s = 0; s < NWARP; s++) {
                float4 v = *(const float4*)&red[((size_t)s * 32 + gb) * 40 + up * 4];
                z.x += v.x; z.y += v.y; z.z += v.z; z.w += v.w;
            }
            float zf = z.x + zx4.x;
            float zi = z.y + zx4.y;
            float zg = z.z + zx4.z;
            float zo = z.w + zx4.w;

            float f = sigmoidf_(zf);
            float ii = sigmoidf_(zi);
            float g = tanhf_(zg);
            float o = sigmoidf_(zo);
            c_state = f * c_state + ii * g;
            h_new = o * tanhf_(c_state);

            __nv_bfloat16 hh = __float2bfloat16(h_new);
            __nv_bfloat16 hl = __float2bfloat16(h_new - __bfloat162float(hh));
            hhio[gb * 1024 + hidx] = hh;
            hloo[gb * 1024 + hidx] = hl;
        }

        // ---- grid barrier (release/acquire) ----
        __syncthreads();   // h stores issued, red consumed
        if (tid == 0) bar_arrive_release(&g_bar);

        if (tid < 256)
            out[((size_t)gb * TT + t) * UU + ug] = h_new;

        if (tid == 0) {
            unsigned target = (unsigned)NCTA * (unsigned)(t + 1);
            while (ld_acquire(&g_bar) < target) {}
        }
        __syncthreads();
    }
#undef LDA
#undef COMPUTE
}

// ===========================================================================
// Launch
// ===========================================================================
extern "C" void kernel_launch(void* const* d_in, const int* in_sizes, int n_in,
                              void* d_out, int out_size) {
    const float* data = (const float*)d_in[0];
    const float* Wf = (const float*)d_in[1];
    const float* bf = (const float*)d_in[2];
    const float* Wi = (const float*)d_in[3];
    const float* bi = (const float*)d_in[4];
    const float* Wc = (const float*)d_in[5];
    const float* bc = (const float*)d_in[6];
    const float* Wo = (const float*)d_in[7];
    const float* bo = (const float*)d_in[8];
    float* out = (float*)d_out;

    static int attr_set = 0;
    const int psmem_bytes = 32 * RPITCH * 2 * 2 + NWARP * 32 * 40 * 4;  // 216064
    if (!attr_set) {
        cudaFuncSetAttribute(lstm_persistent,
                             cudaFuncAttributeMaxDynamicSharedMemorySize, psmem_bytes);
        attr_set = 1;
    }

    prep_kernel<<<512, 256>>>(Wf, Wi, Wc, Wo, bf, bi, bc, bo);
    conv_x_kernel<<<2048, 256>>>(data);

    dim3 zgrid(NC / ZNT, (TT * BB) / ZMT);  // (64, 128)
    zx_mma_kernel<<<zgrid, 256>>>();

    lstm_persistent<<<NCTA, 512, psmem_bytes>>>(out);
}

// round 13
// speedup vs baseline: 1.1716x; 1.1716x over previous
#include <cuda_runtime.h>
#include <cuda_bf16.h>
#include <math.h>
#include <stdint.h>

// Problem constants
#define BB 32
#define TT 512
#define DD 512
#define UU 1024
#define NC 4096   // 4*U packed gate columns, layout [unit][gate], gate order f,i,g,o

#define NCTA 128       // persistent CTAs (1 per SM)
#define NWARP 8        // warps in persistent kernel (R11 best config)
#define WROWB 4160     // smem weight row pitch in BYTES (bank-clean for LDS.128)

// -------- device scratch --------
__device__ float g_bp[4096];                  // packed biases
__device__ float g_zx[(size_t)TT * BB * NC];  // [t][b][u*4+g]  x-part (+bias)
__device__ unsigned g_bar;                    // grid barrier counter
// bf16 hi/lo for tensor-core zx (unchanged from R10/R11)
__device__ __nv_bfloat16 g_xhi[(size_t)TT * BB * DD];  // [row=t*32+b][d]
__device__ __nv_bfloat16 g_xlo[(size_t)TT * BB * DD];
__device__ __nv_bfloat16 g_bwhi[(size_t)NC * DD];      // input W  [c][d]
__device__ __nv_bfloat16 g_bwlo[(size_t)NC * DD];
// PACKED recurrent weights: per row c, 64 chunks x 32 bf16:
//   [tg][ hi(2tg,2tg+1), hi(2tg+8,2tg+9), lo(2tg,2tg+1), lo(2tg+8,2tg+9) ]
__device__ __nv_bfloat16 g_rw[(size_t)NC * 2048];
// PACKED hidden state, ping-pong: per batch b, same chunk packing over u
__device__ __nv_bfloat16 g_hp[2][BB * 2048];

__device__ __forceinline__ float sigmoidf_(float x) {
    return 1.0f / (1.0f + __expf(-x));
}
__device__ __forceinline__ float tanhf_(float x) {
    return 1.0f - 2.0f / (__expf(2.0f * x) + 1.0f);
}

// -------- barrier primitives --------
__device__ __forceinline__ void bar_arrive_release(unsigned* p) {
    unsigned old;
    asm volatile("atom.add.release.gpu.u32 %0, [%1], 1;" : "=r"(old) : "l"(p) : "memory");
}
__device__ __forceinline__ unsigned ld_acquire(unsigned* p) {
    unsigned v;
    asm volatile("ld.acquire.gpu.u32 %0, [%1];" : "=r"(v) : "l"(p) : "memory");
    return v;
}

// -------- mma.sync bf16 --------
__device__ __forceinline__ void mma16816(float* c, const uint32_t* a, const uint32_t* b) {
    asm volatile(
        "mma.sync.aligned.m16n8k16.row.col.f32.bf16.bf16.f32 "
        "{%0,%1,%2,%3}, {%4,%5,%6,%7}, {%8,%9}, {%0,%1,%2,%3};"
        : "+f"(c[0]), "+f"(c[1]), "+f"(c[2]), "+f"(c[3])
        : "r"(a[0]), "r"(a[1]), "r"(a[2]), "r"(a[3]), "r"(b[0]), "r"(b[1]));
}

// ===========================================================================
// Prep: biases, bf16 hi/lo input weights (zx), PACKED recurrent weights,
// zero packed h0 + bar
// ===========================================================================
__global__ void prep_kernel(const float* __restrict__ Wf, const float* __restrict__ Wi,
                            const float* __restrict__ Wc, const float* __restrict__ Wo,
                            const float* __restrict__ bf, const float* __restrict__ bi,
                            const float* __restrict__ bc, const float* __restrict__ bo) {
    int idx = blockIdx.x * blockDim.x + threadIdx.x;
    int stride = gridDim.x * blockDim.x;
    if (idx == 0) g_bar = 0u;
    const float* Ws[4] = {Wf, Wi, Wc, Wo};

    // Input weights -> bf16 hi/lo [c][d] (zx path, unchanged)
    for (int i = idx; i < 512 * 1024; i += stride) {
        int d = i >> 10, u = i & 1023;
        int s = (1024 + d) * 1024 + u;
#pragma unroll
        for (int g = 0; g < 4; g++) {
            float v = Ws[g][s];
            int c = u * 4 + g;
            __nv_bfloat16 h = __float2bfloat16(v);
            g_bwhi[(size_t)c * 512 + d] = h;
            g_bwlo[(size_t)c * 512 + d] = __float2bfloat16(v - __bfloat162float(h));
        }
    }
    // Recurrent weights -> PACKED hi/lo layout
    for (size_t i = idx; i < (size_t)NC * UU; i += stride) {
        int c = (int)(i >> 10), k = (int)(i & 1023);
        int u = c >> 2, g = c & 3;
        float v = Ws[g][(size_t)k * 1024 + u];
        __nv_bfloat16 h = __float2bfloat16(v);
        __nv_bfloat16 l = __float2bfloat16(v - __bfloat162float(h));
        int ch = k >> 4, ii = k & 15;
        int tg = (ii & 6) >> 1, h8 = ii >> 3, sel = ii & 1;
        size_t off = (size_t)c * 2048 + ch * 32 + tg * 8 + h8 * 2 + sel;
        g_rw[off] = h;
        g_rw[off + 4] = l;
    }
    for (int u = idx; u < 1024; u += stride)
        *(float4*)&g_bp[u << 2] = make_float4(bf[u], bi[u], bc[u], bo[u]);
    for (int i = idx; i < BB * 2048; i += stride)
        g_hp[0][i] = __float2bfloat16(0.0f);
}

// ===========================================================================
// Convert x -> bf16 hi/lo, layout [row=t*32+b][d]  (zx path, unchanged)
// ===========================================================================
__global__ void conv_x_kernel(const float* __restrict__ x) {
    int idx = blockIdx.x * blockDim.x + threadIdx.x;
    int stride = gridDim.x * blockDim.x;
    const int N4 = BB * TT * DD / 4;
    for (int i = idx; i < N4; i += stride) {
        int d4 = i & 127;
        int rt = i >> 7;           // b*512 + t
        int b = rt >> 9, t = rt & 511;
        float4 v = *(const float4*)&x[(size_t)i * 4];
        size_t o = ((size_t)(t * 32 + b)) * 512 + d4 * 4;

        __nv_bfloat16 h0 = __float2bfloat16(v.x);
        __nv_bfloat16 h1 = __float2bfloat16(v.y);
        __nv_bfloat16 h2 = __float2bfloat16(v.z);
        __nv_bfloat16 h3 = __float2bfloat16(v.w);
        __nv_bfloat162 hp0; hp0.x = h0; hp0.y = h1;
        __nv_bfloat162 hp1; hp1.x = h2; hp1.y = h3;
        *(__nv_bfloat162*)(g_xhi + o) = hp0;
        *(__nv_bfloat162*)(g_xhi + o + 2) = hp1;

        __nv_bfloat162 lp0, lp1;
        lp0.x = __float2bfloat16(v.x - __bfloat162float(h0));
        lp0.y = __float2bfloat16(v.y - __bfloat162float(h1));
        lp1.x = __float2bfloat16(v.z - __bfloat162float(h2));
        lp1.y = __float2bfloat16(v.w - __bfloat162float(h3));
        *(__nv_bfloat162*)(g_xlo + o) = lp0;
        *(__nv_bfloat162*)(g_xlo + o + 2) = lp1;
    }
}

// ===========================================================================
// zx GEMM via mma.sync (unchanged from R10/R11 win)
// ===========================================================================
#define ZMT 128
#define ZNT 64
#define ZKC 32
#define ZST 40

__global__ __launch_bounds__(256) void zx_mma_kernel() {
    __shared__ __align__(16) __nv_bfloat16 sAhi[ZMT * ZST];
    __shared__ __align__(16) __nv_bfloat16 sAlo[ZMT * ZST];
    __shared__ __align__(16) __nv_bfloat16 sBhi[ZNT * ZST];
    __shared__ __align__(16) __nv_bfloat16 sBlo[ZNT * ZST];

    const int tid = threadIdx.x;
    const int lane = tid & 31;
    const int wid = tid >> 5;
    const int wm = wid >> 1;
    const int wn = wid & 1;
    const int gr = lane >> 2;
    const int tg = lane & 3;
    const int n0 = blockIdx.x * ZNT;
    const int row0 = blockIdx.y * ZMT;

    float c[2][4][4];
#pragma unroll
    for (int mi = 0; mi < 2; mi++)
#pragma unroll
        for (int ni = 0; ni < 4; ni++)
#pragma unroll
            for (int r = 0; r < 4; r++) c[mi][ni][r] = 0.0f;

    for (int kc = 0; kc < DD / ZKC; kc++) {
        __syncthreads();
#pragma unroll
        for (int it = 0; it < 2; it++) {
            int idx = tid + it * 256;
            int r = idx >> 2, q = idx & 3;
            size_t go = ((size_t)(row0 + r)) * 512 + kc * 32 + q * 8;
            *(uint4*)&sAhi[r * ZST + q * 8] = *(const uint4*)(g_xhi + go);
            *(uint4*)&sAlo[r * ZST + q * 8] = *(const uint4*)(g_xlo + go);
        }
        {
            int r = tid >> 2, q = tid & 3;
            size_t go = ((size_t)(n0 + r)) * 512 + kc * 32 + q * 8;
            *(uint4*)&sBhi[r * ZST + q * 8] = *(const uint4*)(g_bwhi + go);
            *(uint4*)&sBlo[r * ZST + q * 8] = *(const uint4*)(g_bwlo + go);
        }
        __syncthreads();

#pragma unroll
        for (int ks = 0; ks < 2; ks++) {
            uint32_t ahi[2][4], alo[2][4];
#pragma unroll
            for (int mi = 0; mi < 2; mi++) {
                int rb = (wm * 32 + mi * 16 + gr) * ZST + ks * 16 + tg * 2;
                ahi[mi][0] = *(const uint32_t*)&sAhi[rb];
                ahi[mi][1] = *(const uint32_t*)&sAhi[rb + 8 * ZST];
                ahi[mi][2] = *(const uint32_t*)&sAhi[rb + 8];
                ahi[mi][3] = *(const uint32_t*)&sAhi[rb + 8 * ZST + 8];
                alo[mi][0] = *(const uint32_t*)&sAlo[rb];
                alo[mi][1] = *(const uint32_t*)&sAlo[rb + 8 * ZST];
                alo[mi][2] = *(const uint32_t*)&sAlo[rb + 8];
                alo[mi][3] = *(const uint32_t*)&sAlo[rb + 8 * ZST + 8];
            }
            uint32_t bhi[4][2], blo[4][2];
#pragma unroll
            for (int ni = 0; ni < 4; ni++) {
                int rb = (wn * 32 + ni * 8 + gr) * ZST + ks * 16 + tg * 2;
                bhi[ni][0] = *(const uint32_t*)&sBhi[rb];
                bhi[ni][1] = *(const uint32_t*)&sBhi[rb + 8];
                blo[ni][0] = *(const uint32_t*)&sBlo[rb];
                blo[ni][1] = *(const uint32_t*)&sBlo[rb + 8];
            }
#pragma unroll
            for (int mi = 0; mi < 2; mi++)
#pragma unroll
                for (int ni = 0; ni < 4; ni++) {
                    mma16816(c[mi][ni], ahi[mi], bhi[ni]);
                    mma16816(c[mi][ni], ahi[mi], blo[ni]);
                    mma16816(c[mi][ni], alo[mi], bhi[ni]);
                }
        }
    }

    const int rbase = row0 + wm * 32;
    const int cbase = n0 + wn * 32;
#pragma unroll
    for (int mi = 0; mi < 2; mi++) {
#pragma unroll
        for (int ni = 0; ni < 4; ni++) {
            int r = rbase + mi * 16 + gr;
            int col = cbase + ni * 8 + tg * 2;
            float2 b01 = *(const float2*)&g_bp[col];
            float2 v0 = make_float2(c[mi][ni][0] + b01.x, c[mi][ni][1] + b01.y);
            float2 v1 = make_float2(c[mi][ni][2] + b01.x, c[mi][ni][3] + b01.y);
            *(float2*)&g_zx[(size_t)r * NC + col] = v0;
            *(float2*)&g_zx[(size_t)(r + 8) * NC + col] = v1;
        }
    }
}

// ===========================================================================
// Persistent recurrent kernel (R11 config: 256 threads / 8 warps), with
// PACKED operands: A = 4x LDG.128, B = 4x LDS.128 per k16 chunk.
// smem: weights 32 rows x 4160B = 133120B + red[8][32][40] fp32 = 174080B
// ===========================================================================
__global__ __launch_bounds__(256, 1) void lstm_persistent(float* __restrict__ out) {
    extern __shared__ __align__(16) char smem[];
    char* wsm = smem;                                   // packed weights
    float* red = (float*)(smem + 32 * WROWB);           // [8][32][40]

    const int tid = threadIdx.x;
    const int cu = blockIdx.x;
    const int lane = tid & 31;
    const int wid = tid >> 5;       // 0..7
    const int gr = lane >> 2;
    const int tg = lane & 3;
    const int ch0 = wid * 8;        // warp K-slice: chunks ch0..ch0+7 (K=128)

    // --- load resident packed weights (rows c = cu*32 .. cu*32+31) ---
    for (int i = tid; i < 32 * 256; i += 256) {
        int lr = i >> 8, q = i & 255;
        *(uint4*)(wsm + lr * WROWB + q * 16) =
            *((const uint4*)(g_rw + (size_t)(cu * 32 + lr) * 2048) + q);
    }

    // --- gate-math roles ---
    const int up = tid >> 5;        // unit-in-CTA 0..7
    const int gb = tid & 31;        // batch 0..31
    const int ug = cu * 8 + up;     // global unit
    // packed h store offsets for value index (within this unit's chunk)
    const int s_ch = ug >> 4;
    const int s_ii = ug & 15;
    const int s_off = s_ch * 32 + ((s_ii & 6) >> 1) * 8 + (s_ii >> 3) * 2 + (s_ii & 1);

    float c_state = 0.0f;
    __syncthreads();                // weights ready

    for (int t = 0; t < TT; t++) {
        const __nv_bfloat16* __restrict__ hp = g_hp[t & 1];
        __nv_bfloat16* __restrict__ hpo = g_hp[(t + 1) & 1];

        float4 zx4 = __ldcg((const float4*)&g_zx[((size_t)t * BB + gb) * NC + ug * 4]);

        float acc[2][4][4];
#pragma unroll
        for (int mi = 0; mi < 2; mi++)
#pragma unroll
            for (int ni = 0; ni < 4; ni++)
#pragma unroll
                for (int r = 0; r < 4; r++) acc[mi][ni][r] = 0.0f;

#define LDA(dst, ch) do { \
        (dst)[0] = __ldcg((const uint4*)(hp + (gr)      * 2048 + (ch) * 32) + tg); \
        (dst)[1] = __ldcg((const uint4*)(hp + (gr + 8)  * 2048 + (ch) * 32) + tg); \
        (dst)[2] = __ldcg((const uint4*)(hp + (gr + 16) * 2048 + (ch) * 32) + tg); \
        (dst)[3] = __ldcg((const uint4*)(hp + (gr + 24) * 2048 + (ch) * 32) + tg); \
    } while (0)

#define COMPUTE(buf, ch) do { \
        uint32_t ah0[4] = {(buf)[0].x, (buf)[1].x, (buf)[0].y, (buf)[1].y}; \
        uint32_t al0[4] = {(buf)[0].z, (buf)[1].z, (buf)[0].w, (buf)[1].w}; \
        uint32_t ah1[4] = {(buf)[2].x, (buf)[3].x, (buf)[2].y, (buf)[3].y}; \
        uint32_t al1[4] = {(buf)[2].z, (buf)[3].z, (buf)[2].w, (buf)[3].w}; \
        _Pragma("unroll") \
        for (int ni = 0; ni < 4; ni++) { \
            uint4 wb = *(const uint4*)(wsm + (ni * 8 + gr) * WROWB + (ch) * 64 + tg * 16); \
            uint32_t bh[2] = {wb.x, wb.y}; \
            uint32_t bl[2] = {wb.z, wb.w}; \
            mma16816(acc[0][ni], ah0, bh); \
            mma16816(acc[0][ni], ah0, bl); \
            mma16816(acc[0][ni], al0, bh); \
            mma16816(acc[1][ni], ah1, bh); \
            mma16816(acc[1][ni], ah1, bl); \
            mma16816(acc[1][ni], al1, bh); \
        } \
    } while (0)

        uint4 cur[4], nxt[4];
        LDA(cur, ch0);
#pragma unroll
        for (int i = 0; i < 8; i += 2) {
            LDA(nxt, ch0 + i + 1);
            COMPUTE(cur, ch0 + i);
            if (i + 2 < 8) LDA(cur, ch0 + i + 2);
            COMPUTE(nxt, ch0 + i + 1);
        }

        // ---- write partials: red[wid][b][40] ----
#pragma unroll
        for (int mi = 0; mi < 2; mi++)
#pragma unroll
            for (int ni = 0; ni < 4; ni++) {
                float* b0 = &red[((size_t)wid * 32 + mi * 16 + gr) * 40 + ni * 8 + tg * 2];
                *(float2*)b0 = make_float2(acc[mi][ni][0], acc[mi][ni][1]);
                *(float2*)(b0 + 8 * 40) = make_float2(acc[mi][ni][2], acc[mi][ni][3]);
            }
        __syncthreads();

        // ---- reduce + gate math: thread = (unit up, batch gb) ----
        float h_new;
        {
            float4 z = make_float4(0.f, 0.f, 0.f, 0.f);
#pragma unroll
            for (int s = 0; s < NWARP; s++) {
                float4 v = *(const float4*)&red[((size_t)s * 32 + gb) * 40 + up * 4];
                z.x += v.x; z.y += v.y; z.z += v.z; z.w += v.w;
            }
            float zf = z.x + zx4.x;
            float zi = z.y + zx4.y;
            float zg = z.z + zx4.z;
            float zo = z.w + zx4.w;

            float f = sigmoidf_(zf);
            float ii = sigmoidf_(zi);
            float g = tanhf_(zg);
            float o = sigmoidf_(zo);
            c_state = f * c_state + ii * g;
            h_new = o * tanhf_(c_state);

            __nv_bfloat16 hh = __float2bfloat16(h_new);
            __nv_bfloat16 hl = __float2bfloat16(h_new - __bfloat162float(hh));
            hpo[gb * 2048 + s_off] = hh;
            hpo[gb * 2048 + s_off + 4] = hl;
        }

        // ---- grid barrier (release/acquire) ----
        __syncthreads();   // h stores issued, red consumed
        if (tid == 0) bar_arrive_release(&g_bar);

        out[((size_t)gb * TT + t) * UU + ug] = h_new;

        if (tid == 0) {
            unsigned target = (unsigned)NCTA * (unsigned)(t + 1);
            while (ld_acquire(&g_bar) < target) {}
        }
        __syncthreads();
    }
#undef LDA
#undef COMPUTE
}

// ===========================================================================
// Launch
// ===========================================================================
extern "C" void kernel_launch(void* const* d_in, const int* in_sizes, int n_in,
                              void* d_out, int out_size) {
    const float* data = (const float*)d_in[0];
    const float* Wf = (const float*)d_in[1];
    const float* bf = (const float*)d_in[2];
    const float* Wi = (const float*)d_in[3];
    const float* bi = (const float*)d_in[4];
    const float* Wc = (const float*)d_in[5];
    const float* bc = (const float*)d_in[6];
    const float* Wo = (const float*)d_in[7];
    const float* bo = (const float*)d_in[8];
    float* out = (float*)d_out;

    static int attr_set = 0;
    const int psmem_bytes = 32 * WROWB + NWARP * 32 * 40 * 4;  // 133120 + 40960 = 174080
    if (!attr_set) {
        cudaFuncSetAttribute(lstm_persistent,
                             cudaFuncAttributeMaxDynamicSharedMemorySize, psmem_bytes);
        attr_set = 1;
    }

    prep_kernel<<<512, 256>>>(Wf, Wi, Wc, Wo, bf, bi, bc, bo);
    conv_x_kernel<<<2048, 256>>>(data);

    dim3 zgrid(NC / ZNT, (TT * BB) / ZMT);  // (64, 128)
    zx_mma_kernel<<<zgrid, 256>>>();

    lstm_persistent<<<NCTA, 256, psmem_bytes>>>(out);
}

// round 14
// speedup vs baseline: 1.3958x; 1.1914x over previous
#include <cuda_runtime.h>
#include <cuda_bf16.h>
#include <cuda_fp16.h>
#include <math.h>
#include <stdint.h>

// Problem constants
#define BB 32
#define TT 512
#define DD 512
#define UU 1024
#define NC 4096   // 4*U packed gate columns, layout [unit][gate], gate order f,i,g,o

#define NCTA 128       // persistent CTAs (1 per SM)
#define NWARP 8        // warps in persistent kernel
#define WROWB 4160     // smem weight row pitch in BYTES (bank-clean for LDS.128)

// -------- device scratch --------
__device__ float g_bp[4096];                  // packed biases
__device__ float g_zx[(size_t)TT * BB * NC];  // [t][b][u*4+g]  x-part (+bias)
__device__ unsigned g_bar;                    // grid barrier counter
// bf16 hi/lo for tensor-core zx (unchanged)
__device__ __nv_bfloat16 g_xhi[(size_t)TT * BB * DD];  // [row=t*32+b][d]
__device__ __nv_bfloat16 g_xlo[(size_t)TT * BB * DD];
__device__ __nv_bfloat16 g_bwhi[(size_t)NC * DD];      // input W  [c][d]
__device__ __nv_bfloat16 g_bwlo[(size_t)NC * DD];
// PACKED recurrent weights (fp16 hi/lo): per row c, 64 chunks x 32 f16:
//   [tg][ hi(2tg,2tg+1), hi(2tg+8,2tg+9), lo(2tg,2tg+1), lo(2tg+8,2tg+9) ]
__device__ __half g_rw[(size_t)NC * 2048];
// PACKED fp16 hidden state, ping-pong: per batch, per chunk-PAIR (32 f16 = 64B):
//   [tg][ ch0 pair(2tg), ch0 pair(2tg+8), ch1 pair(2tg), ch1 pair(2tg+8) ]
__device__ __half g_hp[2][BB * 1024];

__device__ __forceinline__ float sigmoidf_(float x) {
    return 1.0f / (1.0f + __expf(-x));
}
__device__ __forceinline__ float tanhf_(float x) {
    return 1.0f - 2.0f / (__expf(2.0f * x) + 1.0f);
}

// -------- barrier primitives --------
__device__ __forceinline__ void bar_arrive_release(unsigned* p) {
    unsigned old;
    asm volatile("atom.add.release.gpu.u32 %0, [%1], 1;" : "=r"(old) : "l"(p) : "memory");
}
__device__ __forceinline__ unsigned ld_acquire(unsigned* p) {
    unsigned v;
    asm volatile("ld.acquire.gpu.u32 %0, [%1];" : "=r"(v) : "l"(p) : "memory");
    return v;
}

// -------- mma.sync --------
__device__ __forceinline__ void mma16816bf(float* c, const uint32_t* a, const uint32_t* b) {
    asm volatile(
        "mma.sync.aligned.m16n8k16.row.col.f32.bf16.bf16.f32 "
        "{%0,%1,%2,%3}, {%4,%5,%6,%7}, {%8,%9}, {%0,%1,%2,%3};"
        : "+f"(c[0]), "+f"(c[1]), "+f"(c[2]), "+f"(c[3])
        : "r"(a[0]), "r"(a[1]), "r"(a[2]), "r"(a[3]), "r"(b[0]), "r"(b[1]));
}
__device__ __forceinline__ void mma16816h(float* c, const uint32_t* a, const uint32_t* b) {
    asm volatile(
        "mma.sync.aligned.m16n8k16.row.col.f32.f16.f16.f32 "
        "{%0,%1,%2,%3}, {%4,%5,%6,%7}, {%8,%9}, {%0,%1,%2,%3};"
        : "+f"(c[0]), "+f"(c[1]), "+f"(c[2]), "+f"(c[3])
        : "r"(a[0]), "r"(a[1]), "r"(a[2]), "r"(a[3]), "r"(b[0]), "r"(b[1]));
}

// ===========================================================================
// Prep: biases, bf16 hi/lo input weights (zx), PACKED fp16 recurrent weights,
// zero packed h0 + bar
// ===========================================================================
__global__ void prep_kernel(const float* __restrict__ Wf, const float* __restrict__ Wi,
                            const float* __restrict__ Wc, const float* __restrict__ Wo,
                            const float* __restrict__ bf, const float* __restrict__ bi,
                            const float* __restrict__ bc, const float* __restrict__ bo) {
    int idx = blockIdx.x * blockDim.x + threadIdx.x;
    int stride = gridDim.x * blockDim.x;
    if (idx == 0) g_bar = 0u;
    const float* Ws[4] = {Wf, Wi, Wc, Wo};

    // Input weights -> bf16 hi/lo [c][d] (zx path, unchanged)
    for (int i = idx; i < 512 * 1024; i += stride) {
        int d = i >> 10, u = i & 1023;
        int s = (1024 + d) * 1024 + u;
#pragma unroll
        for (int g = 0; g < 4; g++) {
            float v = Ws[g][s];
            int c = u * 4 + g;
            __nv_bfloat16 h = __float2bfloat16(v);
            g_bwhi[(size_t)c * 512 + d] = h;
            g_bwlo[(size_t)c * 512 + d] = __float2bfloat16(v - __bfloat162float(h));
        }
    }
    // Recurrent weights -> PACKED fp16 hi/lo layout (per 16-chunk)
    for (size_t i = idx; i < (size_t)NC * UU; i += stride) {
        int c = (int)(i >> 10), k = (int)(i & 1023);
        int u = c >> 2, g = c & 3;
        float v = Ws[g][(size_t)k * 1024 + u];
        __half h = __float2half(v);
        __half l = __float2half(v - __half2float(h));
        int ch = k >> 4, ii = k & 15;
        int tg = (ii & 6) >> 1, h8 = ii >> 3, sel = ii & 1;
        size_t off = (size_t)c * 2048 + ch * 32 + tg * 8 + h8 * 2 + sel;
        g_rw[off] = h;
        g_rw[off + 4] = l;
    }
    for (int u = idx; u < 1024; u += stride)
        *(float4*)&g_bp[u << 2] = make_float4(bf[u], bi[u], bc[u], bo[u]);
    for (int i = idx; i < BB * 1024; i += stride)
        g_hp[0][i] = __float2half(0.0f);
}

// ===========================================================================
// Convert x -> bf16 hi/lo, layout [row=t*32+b][d]  (zx path, unchanged)
// ===========================================================================
__global__ void conv_x_kernel(const float* __restrict__ x) {
    int idx = blockIdx.x * blockDim.x + threadIdx.x;
    int stride = gridDim.x * blockDim.x;
    const int N4 = BB * TT * DD / 4;
    for (int i = idx; i < N4; i += stride) {
        int d4 = i & 127;
        int rt = i >> 7;           // b*512 + t
        int b = rt >> 9, t = rt & 511;
        float4 v = *(const float4*)&x[(size_t)i * 4];
        size_t o = ((size_t)(t * 32 + b)) * 512 + d4 * 4;

        __nv_bfloat16 h0 = __float2bfloat16(v.x);
        __nv_bfloat16 h1 = __float2bfloat16(v.y);
        __nv_bfloat16 h2 = __float2bfloat16(v.z);
        __nv_bfloat16 h3 = __float2bfloat16(v.w);
        __nv_bfloat162 hp0; hp0.x = h0; hp0.y = h1;
        __nv_bfloat162 hp1; hp1.x = h2; hp1.y = h3;
        *(__nv_bfloat162*)(g_xhi + o) = hp0;
        *(__nv_bfloat162*)(g_xhi + o + 2) = hp1;

        __nv_bfloat162 lp0, lp1;
        lp0.x = __float2bfloat16(v.x - __bfloat162float(h0));
        lp0.y = __float2bfloat16(v.y - __bfloat162float(h1));
        lp1.x = __float2bfloat16(v.z - __bfloat162float(h2));
        lp1.y = __float2bfloat16(v.w - __bfloat162float(h3));
        *(__nv_bfloat162*)(g_xlo + o) = lp0;
        *(__nv_bfloat162*)(g_xlo + o + 2) = lp1;
    }
}

// ===========================================================================
// zx GEMM via mma.sync (unchanged from R10/R13 win)
// ===========================================================================
#define ZMT 128
#define ZNT 64
#define ZKC 32
#define ZST 40

__global__ __launch_bounds__(256) void zx_mma_kernel() {
    __shared__ __align__(16) __nv_bfloat16 sAhi[ZMT * ZST];
    __shared__ __align__(16) __nv_bfloat16 sAlo[ZMT * ZST];
    __shared__ __align__(16) __nv_bfloat16 sBhi[ZNT * ZST];
    __shared__ __align__(16) __nv_bfloat16 sBlo[ZNT * ZST];

    const int tid = threadIdx.x;
    const int lane = tid & 31;
    const int wid = tid >> 5;
    const int wm = wid >> 1;
    const int wn = wid & 1;
    const int gr = lane >> 2;
    const int tg = lane & 3;
    const int n0 = blockIdx.x * ZNT;
    const int row0 = blockIdx.y * ZMT;

    float c[2][4][4];
#pragma unroll
    for (int mi = 0; mi < 2; mi++)
#pragma unroll
        for (int ni = 0; ni < 4; ni++)
#pragma unroll
            for (int r = 0; r < 4; r++) c[mi][ni][r] = 0.0f;

    for (int kc = 0; kc < DD / ZKC; kc++) {
        __syncthreads();
#pragma unroll
        for (int it = 0; it < 2; it++) {
            int idx = tid + it * 256;
            int r = idx >> 2, q = idx & 3;
            size_t go = ((size_t)(row0 + r)) * 512 + kc * 32 + q * 8;
            *(uint4*)&sAhi[r * ZST + q * 8] = *(const uint4*)(g_xhi + go);
            *(uint4*)&sAlo[r * ZST + q * 8] = *(const uint4*)(g_xlo + go);
        }
        {
            int r = tid >> 2, q = tid & 3;
            size_t go = ((size_t)(n0 + r)) * 512 + kc * 32 + q * 8;
            *(uint4*)&sBhi[r * ZST + q * 8] = *(const uint4*)(g_bwhi + go);
            *(uint4*)&sBlo[r * ZST + q * 8] = *(const uint4*)(g_bwlo + go);
        }
        __syncthreads();

#pragma unroll
        for (int ks = 0; ks < 2; ks++) {
            uint32_t ahi[2][4], alo[2][4];
#pragma unroll
            for (int mi = 0; mi < 2; mi++) {
                int rb = (wm * 32 + mi * 16 + gr) * ZST + ks * 16 + tg * 2;
                ahi[mi][0] = *(const uint32_t*)&sAhi[rb];
                ahi[mi][1] = *(const uint32_t*)&sAhi[rb + 8 * ZST];
                ahi[mi][2] = *(const uint32_t*)&sAhi[rb + 8];
                ahi[mi][3] = *(const uint32_t*)&sAhi[rb + 8 * ZST + 8];
                alo[mi][0] = *(const uint32_t*)&sAlo[rb];
                alo[mi][1] = *(const uint32_t*)&sAlo[rb + 8 * ZST];
                alo[mi][2] = *(const uint32_t*)&sAlo[rb + 8];
                alo[mi][3] = *(const uint32_t*)&sAlo[rb + 8 * ZST + 8];
            }
            uint32_t bhi[4][2], blo[4][2];
#pragma unroll
            for (int ni = 0; ni < 4; ni++) {
                int rb = (wn * 32 + ni * 8 + gr) * ZST + ks * 16 + tg * 2;
                bhi[ni][0] = *(const uint32_t*)&sBhi[rb];
                bhi[ni][1] = *(const uint32_t*)&sBhi[rb + 8];
                blo[ni][0] = *(const uint32_t*)&sBlo[rb];
                blo[ni][1] = *(const uint32_t*)&sBlo[rb + 8];
            }
#pragma unroll
            for (int mi = 0; mi < 2; mi++)
#pragma unroll
                for (int ni = 0; ni < 4; ni++) {
                    mma16816bf(c[mi][ni], ahi[mi], bhi[ni]);
                    mma16816bf(c[mi][ni], ahi[mi], blo[ni]);
                    mma16816bf(c[mi][ni], alo[mi], bhi[ni]);
                }
        }
    }

    const int rbase = row0 + wm * 32;
    const int cbase = n0 + wn * 32;
#pragma unroll
    for (int mi = 0; mi < 2; mi++) {
#pragma unroll
        for (int ni = 0; ni < 4; ni++) {
            int r = rbase + mi * 16 + gr;
            int col = cbase + ni * 8 + tg * 2;
            float2 b01 = *(const float2*)&g_bp[col];
            float2 v0 = make_float2(c[mi][ni][0] + b01.x, c[mi][ni][1] + b01.y);
            float2 v1 = make_float2(c[mi][ni][2] + b01.x, c[mi][ni][3] + b01.y);
            *(float2*)&g_zx[(size_t)r * NC + col] = v0;
            *(float2*)&g_zx[(size_t)(r + 8) * NC + col] = v1;
        }
    }
}

// ===========================================================================
// Persistent recurrent kernel (256 threads / 8 warps), fp16 x2:
//   z = (Whi + Wlo) . h_f16.   A = 4x LDG.128 per chunk-PAIR; B = LDS.128.
// smem: weights 32 x 4160B = 133120B + red[8][32][40] fp32 = 174080B
// ===========================================================================
__global__ __launch_bounds__(256, 1) void lstm_persistent(float* __restrict__ out) {
    extern __shared__ __align__(16) char smem[];
    char* wsm = smem;                                   // packed weights
    float* red = (float*)(smem + 32 * WROWB);           // [8][32][40]

    const int tid = threadIdx.x;
    const int cu = blockIdx.x;
    const int lane = tid & 31;
    const int wid = tid >> 5;       // 0..7
    const int gr = lane >> 2;
    const int tg = lane & 3;
    const int cp0 = wid * 4;        // warp K-slice: chunk-pairs cp0..cp0+3 (K=128)

    // --- load resident packed weights ---
    for (int i = tid; i < 32 * 256; i += 256) {
        int lr = i >> 8, q = i & 255;
        *(uint4*)(wsm + lr * WROWB + q * 16) =
            *((const uint4*)(g_rw + (size_t)(cu * 32 + lr) * 2048) + q);
    }

    // --- gate-math roles ---
    const int up = tid >> 5;        // unit-in-CTA 0..7
    const int gb = tid & 31;        // batch 0..31
    const int ug = cu * 8 + up;     // global unit
    // packed h store offset: chunk-pair layout
    const int s_chp = ug >> 5;
    const int s_chip = (ug >> 4) & 1;
    const int s_ii = ug & 15;
    const int s_off = s_chp * 32 + ((s_ii & 6) >> 1) * 8 + s_chip * 4 + (s_ii >> 3) * 2 + (s_ii & 1);

    float c_state = 0.0f;
    __syncthreads();                // weights ready

    for (int t = 0; t < TT; t++) {
        const __half* __restrict__ hp = g_hp[t & 1];
        __half* __restrict__ hpo = g_hp[(t + 1) & 1];

        float4 zx4 = __ldcg((const float4*)&g_zx[((size_t)t * BB + gb) * NC + ug * 4]);

        float acc[2][4][4];
#pragma unroll
        for (int mi = 0; mi < 2; mi++)
#pragma unroll
            for (int ni = 0; ni < 4; ni++)
#pragma unroll
                for (int r = 0; r < 4; r++) acc[mi][ni][r] = 0.0f;

// LDA: one chunk-pair (2 k16 chunks) in 4 LDG.128
#define LDA(dst, chp) do { \
        (dst)[0] = __ldcg((const uint4*)(hp + (gr)      * 1024 + (chp) * 32) + tg); \
        (dst)[1] = __ldcg((const uint4*)(hp + (gr + 8)  * 1024 + (chp) * 32) + tg); \
        (dst)[2] = __ldcg((const uint4*)(hp + (gr + 16) * 1024 + (chp) * 32) + tg); \
        (dst)[3] = __ldcg((const uint4*)(hp + (gr + 24) * 1024 + (chp) * 32) + tg); \
    } while (0)

// COMPUTE one chunk: half==0 -> .x/.y of buf, half==1 -> .z/.w
#define COMPUTE(buf, ch, half) do { \
        uint32_t a0[4], a1[4]; \
        if (half == 0) { \
            a0[0] = (buf)[0].x; a0[1] = (buf)[1].x; a0[2] = (buf)[0].y; a0[3] = (buf)[1].y; \
            a1[0] = (buf)[2].x; a1[1] = (buf)[3].x; a1[2] = (buf)[2].y; a1[3] = (buf)[3].y; \
        } else { \
            a0[0] = (buf)[0].z; a0[1] = (buf)[1].z; a0[2] = (buf)[0].w; a0[3] = (buf)[1].w; \
            a1[0] = (buf)[2].z; a1[1] = (buf)[3].z; a1[2] = (buf)[2].w; a1[3] = (buf)[3].w; \
        } \
        _Pragma("unroll") \
        for (int ni = 0; ni < 4; ni++) { \
            uint4 wb = *(const uint4*)(wsm + (ni * 8 + gr) * WROWB + (ch) * 64 + tg * 16); \
            uint32_t bh[2] = {wb.x, wb.y}; \
            uint32_t bl[2] = {wb.z, wb.w}; \
            mma16816h(acc[0][ni], a0, bh); \
            mma16816h(acc[0][ni], a0, bl); \
            mma16816h(acc[1][ni], a1, bh); \
            mma16816h(acc[1][ni], a1, bl); \
        } \
    } while (0)

        uint4 cur[4], nxt[4];
        LDA(cur, cp0);
#pragma unroll
        for (int i = 0; i < 4; i += 2) {
            LDA(nxt, cp0 + i + 1);
            COMPUTE(cur, (cp0 + i) * 2, 0);
            COMPUTE(cur, (cp0 + i) * 2 + 1, 1);
            if (i + 2 < 4) LDA(cur, cp0 + i + 2);
            COMPUTE(nxt, (cp0 + i + 1) * 2, 0);
            COMPUTE(nxt, (cp0 + i + 1) * 2 + 1, 1);
        }

        // ---- write partials: red[wid][b][40] ----
#pragma unroll
        for (int mi = 0; mi < 2; mi++)
#pragma unroll
            for (int ni = 0; ni < 4; ni++) {
                float* b0 = &red[((size_t)wid * 32 + mi * 16 + gr) * 40 + ni * 8 + tg * 2];
                *(float2*)b0 = make_float2(acc[mi][ni][0], acc[mi][ni][1]);
                *(float2*)(b0 + 8 * 40) = make_float2(acc[mi][ni][2], acc[mi][ni][3]);
            }
        __syncthreads();

        // ---- reduce + gate math: thread = (unit up, batch gb) ----
        float h_new;
        {
            float4 z = make_float4(0.f, 0.f, 0.f, 0.f);
#pragma unroll
            for (int s = 0; s < NWARP; s++) {
                float4 v = *(const float4*)&red[((size_t)s * 32 + gb) * 40 + up * 4];
                z.x += v.x; z.y += v.y; z.z += v.z; z.w += v.w;
            }
            float zf = z.x + zx4.x;
            float zi = z.y + zx4.y;
            float zg = z.z + zx4.z;
            float zo = z.w + zx4.w;

            float f = sigmoidf_(zf);
            float ii = sigmoidf_(zi);
            float g = tanhf_(zg);
            float o = sigmoidf_(zo);
            c_state = f * c_state + ii * g;
            h_new = o * tanhf_(c_state);

            hpo[gb * 1024 + s_off] = __float2half(h_new);
        }

        // ---- grid barrier (release/acquire) ----
        __syncthreads();   // h stores issued, red consumed
        if (tid == 0) bar_arrive_release(&g_bar);

        out[((size_t)gb * TT + t) * UU + ug] = h_new;

        if (tid == 0) {
            unsigned target = (unsigned)NCTA * (unsigned)(t + 1);
            while (ld_acquire(&g_bar) < target) {}
        }
        __syncthreads();
    }
#undef LDA
#undef COMPUTE
}

// ===========================================================================
// Launch
// ===========================================================================
extern "C" void kernel_launch(void* const* d_in, const int* in_sizes, int n_in,
                              void* d_out, int out_size) {
    const float* data = (const float*)d_in[0];
    const float* Wf = (const float*)d_in[1];
    const float* bf = (const float*)d_in[2];
    const float* Wi = (const float*)d_in[3];
    const float* bi = (const float*)d_in[4];
    const float* Wc = (const float*)d_in[5];
    const float* bc = (const float*)d_in[6];
    const float* Wo = (const float*)d_in[7];
    const float* bo = (const float*)d_in[8];
    float* out = (float*)d_out;

    static int attr_set = 0;
    const int psmem_bytes = 32 * WROWB + NWARP * 32 * 40 * 4;  // 174080
    if (!attr_set) {
        cudaFuncSetAttribute(lstm_persistent,
                             cudaFuncAttributeMaxDynamicSharedMemorySize, psmem_bytes);
        attr_set = 1;
    }

    prep_kernel<<<512, 256>>>(Wf, Wi, Wc, Wo, bf, bi, bc, bo);
    conv_x_kernel<<<2048, 256>>>(data);

    dim3 zgrid(NC / ZNT, (TT * BB) / ZMT);  // (64, 128)
    zx_mma_kernel<<<zgrid, 256>>>();

    lstm_persistent<<<NCTA, 256, psmem_bytes>>>(out);
}

// round 15
// speedup vs baseline: 1.5115x; 1.0829x over previous
#include <cuda_runtime.h>
#include <cuda_bf16.h>
#include <cuda_fp16.h>
#include <math.h>
#include <stdint.h>

// Problem constants
#define BB 32
#define TT 512
#define DD 512
#define UU 1024
#define NC 4096   // 4*U packed gate columns, layout [unit][gate], gate order f,i,g,o

#define NCTA 128       // persistent CTAs (1 per SM)
#define NWARP 8        // warps in persistent kernel
#define WROWB 2112     // smem weight row pitch in BYTES (2048 + 64; bank-clean LDS.128)

// -------- device scratch --------
__device__ float g_bp[4096];                  // packed biases
__device__ float g_zx[(size_t)TT * BB * NC];  // [t][b][u*4+g]  x-part (+bias)
__device__ unsigned g_bar;                    // grid barrier counter
// bf16 hi/lo for tensor-core zx (unchanged)
__device__ __nv_bfloat16 g_xhi[(size_t)TT * BB * DD];  // [row=t*32+b][d]
__device__ __nv_bfloat16 g_xlo[(size_t)TT * BB * DD];
__device__ __nv_bfloat16 g_bwhi[(size_t)NC * DD];      // input W  [c][d]
__device__ __nv_bfloat16 g_bwlo[(size_t)NC * DD];
// PACKED single-f16 recurrent weights: per row c, chunk-pair packing
//   (identical scheme to h): 32 chunk-pairs x 32 f16 (64B each)
__device__ __half g_rw[(size_t)NC * 1024];
// PACKED fp16 hidden state, ping-pong: per batch, chunk-pair packing
__device__ __half g_hp[2][BB * 1024];

__device__ __forceinline__ float sigmoidf_(float x) {
    return 1.0f / (1.0f + __expf(-x));
}
__device__ __forceinline__ float tanhf_(float x) {
    return 1.0f - 2.0f / (__expf(2.0f * x) + 1.0f);
}

// -------- barrier primitives --------
__device__ __forceinline__ void bar_arrive_release(unsigned* p) {
    unsigned old;
    asm volatile("atom.add.release.gpu.u32 %0, [%1], 1;" : "=r"(old) : "l"(p) : "memory");
}
__device__ __forceinline__ unsigned ld_acquire(unsigned* p) {
    unsigned v;
    asm volatile("ld.acquire.gpu.u32 %0, [%1];" : "=r"(v) : "l"(p) : "memory");
    return v;
}

// -------- mma.sync --------
__device__ __forceinline__ void mma16816bf(float* c, const uint32_t* a, const uint32_t* b) {
    asm volatile(
        "mma.sync.aligned.m16n8k16.row.col.f32.bf16.bf16.f32 "
        "{%0,%1,%2,%3}, {%4,%5,%6,%7}, {%8,%9}, {%0,%1,%2,%3};"
        : "+f"(c[0]), "+f"(c[1]), "+f"(c[2]), "+f"(c[3])
        : "r"(a[0]), "r"(a[1]), "r"(a[2]), "r"(a[3]), "r"(b[0]), "r"(b[1]));
}
__device__ __forceinline__ void mma16816h(float* c, const uint32_t* a, const uint32_t* b) {
    asm volatile(
        "mma.sync.aligned.m16n8k16.row.col.f32.f16.f16.f32 "
        "{%0,%1,%2,%3}, {%4,%5,%6,%7}, {%8,%9}, {%0,%1,%2,%3};"
        : "+f"(c[0]), "+f"(c[1]), "+f"(c[2]), "+f"(c[3])
        : "r"(a[0]), "r"(a[1]), "r"(a[2]), "r"(a[3]), "r"(b[0]), "r"(b[1]));
}

// ===========================================================================
// Prep: biases, bf16 hi/lo input weights (zx), PACKED single-f16 recurrent
// weights, zero packed h0 + bar
// ===========================================================================
__global__ void prep_kernel(const float* __restrict__ Wf, const float* __restrict__ Wi,
                            const float* __restrict__ Wc, const float* __restrict__ Wo,
                            const float* __restrict__ bf, const float* __restrict__ bi,
                            const float* __restrict__ bc, const float* __restrict__ bo) {
    int idx = blockIdx.x * blockDim.x + threadIdx.x;
    int stride = gridDim.x * blockDim.x;
    if (idx == 0) g_bar = 0u;
    const float* Ws[4] = {Wf, Wi, Wc, Wo};

    // Input weights -> bf16 hi/lo [c][d] (zx path, unchanged)
    for (int i = idx; i < 512 * 1024; i += stride) {
        int d = i >> 10, u = i & 1023;
        int s = (1024 + d) * 1024 + u;
#pragma unroll
        for (int g = 0; g < 4; g++) {
            float v = Ws[g][s];
            int c = u * 4 + g;
            __nv_bfloat16 h = __float2bfloat16(v);
            g_bwhi[(size_t)c * 512 + d] = h;
            g_bwlo[(size_t)c * 512 + d] = __float2bfloat16(v - __bfloat162float(h));
        }
    }
    // Recurrent weights -> PACKED single-f16, chunk-pair layout (mirrors h)
    for (size_t i = idx; i < (size_t)NC * UU; i += stride) {
        int c = (int)(i >> 10), k = (int)(i & 1023);
        int u = c >> 2, g = c & 3;
        float v = Ws[g][(size_t)k * 1024 + u];
        int chp = k >> 5, chip = (k >> 4) & 1, ii = k & 15;
        int tg = (ii & 6) >> 1, h8 = ii >> 3, sel = ii & 1;
        size_t off = (size_t)c * 1024 + chp * 32 + tg * 8 + chip * 4 + h8 * 2 + sel;
        g_rw[off] = __float2half(v);
    }
    for (int u = idx; u < 1024; u += stride)
        *(float4*)&g_bp[u << 2] = make_float4(bf[u], bi[u], bc[u], bo[u]);
    for (int i = idx; i < BB * 1024; i += stride)
        g_hp[0][i] = __float2half(0.0f);
}

// ===========================================================================
// Convert x -> bf16 hi/lo, layout [row=t*32+b][d]  (zx path, unchanged)
// ===========================================================================
__global__ void conv_x_kernel(const float* __restrict__ x) {
    int idx = blockIdx.x * blockDim.x + threadIdx.x;
    int stride = gridDim.x * blockDim.x;
    const int N4 = BB * TT * DD / 4;
    for (int i = idx; i < N4; i += stride) {
        int d4 = i & 127;
        int rt = i >> 7;           // b*512 + t
        int b = rt >> 9, t = rt & 511;
        float4 v = *(const float4*)&x[(size_t)i * 4];
        size_t o = ((size_t)(t * 32 + b)) * 512 + d4 * 4;

        __nv_bfloat16 h0 = __float2bfloat16(v.x);
        __nv_bfloat16 h1 = __float2bfloat16(v.y);
        __nv_bfloat16 h2 = __float2bfloat16(v.z);
        __nv_bfloat16 h3 = __float2bfloat16(v.w);
        __nv_bfloat162 hp0; hp0.x = h0; hp0.y = h1;
        __nv_bfloat162 hp1; hp1.x = h2; hp1.y = h3;
        *(__nv_bfloat162*)(g_xhi + o) = hp0;
        *(__nv_bfloat162*)(g_xhi + o + 2) = hp1;

        __nv_bfloat162 lp0, lp1;
        lp0.x = __float2bfloat16(v.x - __bfloat162float(h0));
        lp0.y = __float2bfloat16(v.y - __bfloat162float(h1));
        lp1.x = __float2bfloat16(v.z - __bfloat162float(h2));
        lp1.y = __float2bfloat16(v.w - __bfloat162float(h3));
        *(__nv_bfloat162*)(g_xlo + o) = lp0;
        *(__nv_bfloat162*)(g_xlo + o + 2) = lp1;
    }
}

// ===========================================================================
// zx GEMM via mma.sync (unchanged from R10/R13 win)
// ===========================================================================
#define ZMT 128
#define ZNT 64
#define ZKC 32
#define ZST 40

__global__ __launch_bounds__(256) void zx_mma_kernel() {
    __shared__ __align__(16) __nv_bfloat16 sAhi[ZMT * ZST];
    __shared__ __align__(16) __nv_bfloat16 sAlo[ZMT * ZST];
    __shared__ __align__(16) __nv_bfloat16 sBhi[ZNT * ZST];
    __shared__ __align__(16) __nv_bfloat16 sBlo[ZNT * ZST];

    const int tid = threadIdx.x;
    const int lane = tid & 31;
    const int wid = tid >> 5;
    const int wm = wid >> 1;
    const int wn = wid & 1;
    const int gr = lane >> 2;
    const int tg = lane & 3;
    const int n0 = blockIdx.x * ZNT;
    const int row0 = blockIdx.y * ZMT;

    float c[2][4][4];
#pragma unroll
    for (int mi = 0; mi < 2; mi++)
#pragma unroll
        for (int ni = 0; ni < 4; ni++)
#pragma unroll
            for (int r = 0; r < 4; r++) c[mi][ni][r] = 0.0f;

    for (int kc = 0; kc < DD / ZKC; kc++) {
        __syncthreads();
#pragma unroll
        for (int it = 0; it < 2; it++) {
            int idx = tid + it * 256;
            int r = idx >> 2, q = idx & 3;
            size_t go = ((size_t)(row0 + r)) * 512 + kc * 32 + q * 8;
            *(uint4*)&sAhi[r * ZST + q * 8] = *(const uint4*)(g_xhi + go);
            *(uint4*)&sAlo[r * ZST + q * 8] = *(const uint4*)(g_xlo + go);
        }
        {
            int r = tid >> 2, q = tid & 3;
            size_t go = ((size_t)(n0 + r)) * 512 + kc * 32 + q * 8;
            *(uint4*)&sBhi[r * ZST + q * 8] = *(const uint4*)(g_bwhi + go);
            *(uint4*)&sBlo[r * ZST + q * 8] = *(const uint4*)(g_bwlo + go);
        }
        __syncthreads();

#pragma unroll
        for (int ks = 0; ks < 2; ks++) {
            uint32_t ahi[2][4], alo[2][4];
#pragma unroll
            for (int mi = 0; mi < 2; mi++) {
                int rb = (wm * 32 + mi * 16 + gr) * ZST + ks * 16 + tg * 2;
                ahi[mi][0] = *(const uint32_t*)&sAhi[rb];
                ahi[mi][1] = *(const uint32_t*)&sAhi[rb + 8 * ZST];
                ahi[mi][2] = *(const uint32_t*)&sAhi[rb + 8];
                ahi[mi][3] = *(const uint32_t*)&sAhi[rb + 8 * ZST + 8];
                alo[mi][0] = *(const uint32_t*)&sAlo[rb];
                alo[mi][1] = *(const uint32_t*)&sAlo[rb + 8 * ZST];
                alo[mi][2] = *(const uint32_t*)&sAlo[rb + 8];
                alo[mi][3] = *(const uint32_t*)&sAlo[rb + 8 * ZST + 8];
            }
            uint32_t bhi[4][2], blo[4][2];
#pragma unroll
            for (int ni = 0; ni < 4; ni++) {
                int rb = (wn * 32 + ni * 8 + gr) * ZST + ks * 16 + tg * 2;
                bhi[ni][0] = *(const uint32_t*)&sBhi[rb];
                bhi[ni][1] = *(const uint32_t*)&sBhi[rb + 8];
                blo[ni][0] = *(const uint32_t*)&sBlo[rb];
                blo[ni][1] = *(const uint32_t*)&sBlo[rb + 8];
            }
#pragma unroll
            for (int mi = 0; mi < 2; mi++)
#pragma unroll
                for (int ni = 0; ni < 4; ni++) {
                    mma16816bf(c[mi][ni], ahi[mi], bhi[ni]);
                    mma16816bf(c[mi][ni], ahi[mi], blo[ni]);
                    mma16816bf(c[mi][ni], alo[mi], bhi[ni]);
                }
        }
    }

    const int rbase = row0 + wm * 32;
    const int cbase = n0 + wn * 32;
#pragma unroll
    for (int mi = 0; mi < 2; mi++) {
#pragma unroll
        for (int ni = 0; ni < 4; ni++) {
            int r = rbase + mi * 16 + gr;
            int col = cbase + ni * 8 + tg * 2;
            float2 b01 = *(const float2*)&g_bp[col];
            float2 v0 = make_float2(c[mi][ni][0] + b01.x, c[mi][ni][1] + b01.y);
            float2 v1 = make_float2(c[mi][ni][2] + b01.x, c[mi][ni][3] + b01.y);
            *(float2*)&g_zx[(size_t)r * NC + col] = v0;
            *(float2*)&g_zx[(size_t)(r + 8) * NC + col] = v1;
        }
    }
}

// ===========================================================================
// Persistent recurrent kernel (256 threads / 8 warps), single-product f16:
//   z = W_f16 . h_f16  (fp32 accum).
// Per chunk-pair per warp: 4 LDG.128 (A) + 4 LDS.128 (B) + 16 HMMA.
// smem: weights 32 x 2112B = 67584B + red[8][32][40] fp32 40960B = 108544B
// ===========================================================================
__global__ __launch_bounds__(256, 1) void lstm_persistent(float* __restrict__ out) {
    extern __shared__ __align__(16) char smem[];
    char* wsm = smem;                                   // packed weights
    float* red = (float*)(smem + 32 * WROWB);           // [8][32][40]

    const int tid = threadIdx.x;
    const int cu = blockIdx.x;
    const int lane = tid & 31;
    const int wid = tid >> 5;       // 0..7
    const int gr = lane >> 2;
    const int tg = lane & 3;
    const int cp0 = wid * 4;        // warp K-slice: chunk-pairs cp0..cp0+3 (K=128)

    // --- load resident packed weights (rows c = cu*32 .. cu*32+31) ---
    for (int i = tid; i < 32 * 128; i += 256) {
        int lr = i >> 7, q = i & 127;
        *(uint4*)(wsm + lr * WROWB + q * 16) =
            *((const uint4*)(g_rw + (size_t)(cu * 32 + lr) * 1024) + q);
    }

    // --- gate-math roles ---
    const int up = tid >> 5;        // unit-in-CTA 0..7
    const int gb = tid & 31;        // batch 0..31
    const int ug = cu * 8 + up;     // global unit
    // packed h store offset (chunk-pair layout)
    const int s_chp = ug >> 5;
    const int s_chip = (ug >> 4) & 1;
    const int s_ii = ug & 15;
    const int s_off = s_chp * 32 + ((s_ii & 6) >> 1) * 8 + s_chip * 4 + (s_ii >> 3) * 2 + (s_ii & 1);

    float c_state = 0.0f;
    __syncthreads();                // weights ready

    for (int t = 0; t < TT; t++) {
        const __half* __restrict__ hp = g_hp[t & 1];
        __half* __restrict__ hpo = g_hp[(t + 1) & 1];

        float4 zx4 = __ldcg((const float4*)&g_zx[((size_t)t * BB + gb) * NC + ug * 4]);

        float acc[2][4][4];
#pragma unroll
        for (int mi = 0; mi < 2; mi++)
#pragma unroll
            for (int ni = 0; ni < 4; ni++)
#pragma unroll
                for (int r = 0; r < 4; r++) acc[mi][ni][r] = 0.0f;

// LDA: one chunk-pair (2 k16 chunks) in 4 LDG.128
#define LDA(dst, chp) do { \
        (dst)[0] = __ldcg((const uint4*)(hp + (gr)      * 1024 + (chp) * 32) + tg); \
        (dst)[1] = __ldcg((const uint4*)(hp + (gr + 8)  * 1024 + (chp) * 32) + tg); \
        (dst)[2] = __ldcg((const uint4*)(hp + (gr + 16) * 1024 + (chp) * 32) + tg); \
        (dst)[3] = __ldcg((const uint4*)(hp + (gr + 24) * 1024 + (chp) * 32) + tg); \
    } while (0)

// COMPUTE one chunk-pair: A frags from buf (.x/.y = chunk0, .z/.w = chunk1);
// B frags: one LDS.128 per ni gives both chunks.
#define COMPUTE(buf, chp) do { \
        uint32_t a0c0[4] = {(buf)[0].x, (buf)[1].x, (buf)[0].y, (buf)[1].y}; \
        uint32_t a1c0[4] = {(buf)[2].x, (buf)[3].x, (buf)[2].y, (buf)[3].y}; \
        uint32_t a0c1[4] = {(buf)[0].z, (buf)[1].z, (buf)[0].w, (buf)[1].w}; \
        uint32_t a1c1[4] = {(buf)[2].z, (buf)[3].z, (buf)[2].w, (buf)[3].w}; \
        _Pragma("unroll") \
        for (int ni = 0; ni < 4; ni++) { \
            uint4 wb = *(const uint4*)(wsm + (ni * 8 + gr) * WROWB + (chp) * 64 + tg * 16); \
            uint32_t b0[2] = {wb.x, wb.y}; \
            uint32_t b1[2] = {wb.z, wb.w}; \
            mma16816h(acc[0][ni], a0c0, b0); \
            mma16816h(acc[1][ni], a1c0, b0); \
            mma16816h(acc[0][ni], a0c1, b1); \
            mma16816h(acc[1][ni], a1c1, b1); \
        } \
    } while (0)

        uint4 cur[4], nxt[4];
        LDA(cur, cp0);
#pragma unroll
        for (int i = 0; i < 4; i += 2) {
            LDA(nxt, cp0 + i + 1);
            COMPUTE(cur, cp0 + i);
            if (i + 2 < 4) LDA(cur, cp0 + i + 2);
            COMPUTE(nxt, cp0 + i + 1);
        }

        // ---- write partials: red[wid][b][40] ----
#pragma unroll
        for (int mi = 0; mi < 2; mi++)
#pragma unroll
            for (int ni = 0; ni < 4; ni++) {
                float* b0 = &red[((size_t)wid * 32 + mi * 16 + gr) * 40 + ni * 8 + tg * 2];
                *(float2*)b0 = make_float2(acc[mi][ni][0], acc[mi][ni][1]);
                *(float2*)(b0 + 8 * 40) = make_float2(acc[mi][ni][2], acc[mi][ni][3]);
            }
        __syncthreads();

        // ---- reduce + gate math: thread = (unit up, batch gb) ----
        float h_new;
        {
            float4 z = make_float4(0.f, 0.f, 0.f, 0.f);
#pragma unroll
            for (int s = 0; s < NWARP; s++) {
                float4 v = *(const float4*)&red[((size_t)s * 32 + gb) * 40 + up * 4];
                z.x += v.x; z.y += v.y; z.z += v.z; z.w += v.w;
            }
            float zf = z.x + zx4.x;
            float zi = z.y + zx4.y;
            float zg = z.z + zx4.z;
            float zo = z.w + zx4.w;

            float f = sigmoidf_(zf);
            float ii = sigmoidf_(zi);
            float g = tanhf_(zg);
            float o = sigmoidf_(zo);
            c_state = f * c_state + ii * g;
            h_new = o * tanhf_(c_state);

            hpo[gb * 1024 + s_off] = __float2half(h_new);
        }

        // ---- grid barrier (release/acquire) ----
        __syncthreads();   // h stores issued, red consumed
        if (tid == 0) bar_arrive_release(&g_bar);

        out[((size_t)gb * TT + t) * UU + ug] = h_new;

        if (tid == 0) {
            unsigned target = (unsigned)NCTA * (unsigned)(t + 1);
            while (ld_acquire(&g_bar) < target) {}
        }
        __syncthreads();
    }
#undef LDA
#undef COMPUTE
}

// ===========================================================================
// Launch
// ===========================================================================
extern "C" void kernel_launch(void* const* d_in, const int* in_sizes, int n_in,
                              void* d_out, int out_size) {
    const float* data = (const float*)d_in[0];
    const float* Wf = (const float*)d_in[1];
    const float* bf = (const float*)d_in[2];
    const float* Wi = (const float*)d_in[3];
    const float* bi = (const float*)d_in[4];
    const float* Wc = (const float*)d_in[5];
    const float* bc = (const float*)d_in[6];
    const float* Wo = (const float*)d_in[7];
    const float* bo = (const float*)d_in[8];
    float* out = (float*)d_out;

    static int attr_set = 0;
    const int psmem_bytes = 32 * WROWB + NWARP * 32 * 40 * 4;  // 67584 + 40960 = 108544
    if (!attr_set) {
        cudaFuncSetAttribute(lstm_persistent,
                             cudaFuncAttributeMaxDynamicSharedMemorySize, psmem_bytes);
        attr_set = 1;
    }

    prep_kernel<<<512, 256>>>(Wf, Wi, Wc, Wo, bf, bi, bc, bo);
    conv_x_kernel<<<2048, 256>>>(data);

    dim3 zgrid(NC / ZNT, (TT * BB) / ZMT);  // (64, 128)
    zx_mma_kernel<<<zgrid, 256>>>();

    lstm_persistent<<<NCTA, 256, psmem_bytes>>>(out);
}

// round 16
// speedup vs baseline: 1.8077x; 1.1959x over previous
#include <cuda_runtime.h>
#include <cuda_bf16.h>
#include <cuda_fp16.h>
#include <math.h>
#include <stdint.h>

// Problem constants
#define BB 32
#define TT 512
#define DD 512
#define UU 1024
#define NC 4096   // 4*U packed gate columns, layout [unit][gate], gate order f,i,g,o

#define NCTA 128       // persistent CTAs (1 per SM)
#define NWARP 8        // warps in persistent kernel
#define WROWB 2112     // smem weight row pitch in BYTES (bank-clean LDS.128)

// -------- device scratch --------
__device__ float g_bp[4096];                  // packed biases
__device__ float g_zx[(size_t)TT * BB * NC];  // [t][b][u*4+g]  x-part (+bias)
__device__ unsigned g_bar;                    // grid barrier counter
// f16 operands for zx GEMM (single precision stream)
__device__ __half g_x[(size_t)TT * BB * DD];  // [row=t*32+b][d]
__device__ __half g_bw[(size_t)NC * DD];      // input W  [c][d]
// PACKED single-f16 recurrent weights: chunk-pair packing (32 cp x 32 f16)
__device__ __half g_rw[(size_t)NC * 1024];
// PACKED fp16 hidden state, ping-pong: per batch, chunk-pair packing
__device__ __half g_hp[2][BB * 1024];

__device__ __forceinline__ float sigmoidf_(float x) {
    return 1.0f / (1.0f + __expf(-x));
}
__device__ __forceinline__ float tanhf_(float x) {
    return 1.0f - 2.0f / (__expf(2.0f * x) + 1.0f);
}

// -------- barrier primitives --------
__device__ __forceinline__ void bar_arrive_release(unsigned* p) {
    unsigned old;
    asm volatile("atom.add.release.gpu.u32 %0, [%1], 1;" : "=r"(old) : "l"(p) : "memory");
}
__device__ __forceinline__ unsigned ld_acquire(unsigned* p) {
    unsigned v;
    asm volatile("ld.acquire.gpu.u32 %0, [%1];" : "=r"(v) : "l"(p) : "memory");
    return v;
}

// -------- mma.sync f16 --------
__device__ __forceinline__ void mma16816h(float* c, const uint32_t* a, const uint32_t* b) {
    asm volatile(
        "mma.sync.aligned.m16n8k16.row.col.f32.f16.f16.f32 "
        "{%0,%1,%2,%3}, {%4,%5,%6,%7}, {%8,%9}, {%0,%1,%2,%3};"
        : "+f"(c[0]), "+f"(c[1]), "+f"(c[2]), "+f"(c[3])
        : "r"(a[0]), "r"(a[1]), "r"(a[2]), "r"(a[3]), "r"(b[0]), "r"(b[1]));
}

// ===========================================================================
// Prep: biases, f16 input weights (zx), PACKED f16 recurrent weights,
// zero packed h0 + bar
// ===========================================================================
__global__ void prep_kernel(const float* __restrict__ Wf, const float* __restrict__ Wi,
                            const float* __restrict__ Wc, const float* __restrict__ Wo,
                            const float* __restrict__ bf, const float* __restrict__ bi,
                            const float* __restrict__ bc, const float* __restrict__ bo) {
    int idx = blockIdx.x * blockDim.x + threadIdx.x;
    int stride = gridDim.x * blockDim.x;
    if (idx == 0) g_bar = 0u;
    const float* Ws[4] = {Wf, Wi, Wc, Wo};

    // Input weights -> single f16 [c][d]
    for (int i = idx; i < 512 * 1024; i += stride) {
        int d = i >> 10, u = i & 1023;
        int s = (1024 + d) * 1024 + u;
#pragma unroll
        for (int g = 0; g < 4; g++) {
            int c = u * 4 + g;
            g_bw[(size_t)c * 512 + d] = __float2half(Ws[g][s]);
        }
    }
    // Recurrent weights -> PACKED single-f16, chunk-pair layout (mirrors h)
    for (size_t i = idx; i < (size_t)NC * UU; i += stride) {
        int c = (int)(i >> 10), k = (int)(i & 1023);
        int u = c >> 2, g = c & 3;
        float v = Ws[g][(size_t)k * 1024 + u];
        int chp = k >> 5, chip = (k >> 4) & 1, ii = k & 15;
        int tg = (ii & 6) >> 1, h8 = ii >> 3, sel = ii & 1;
        size_t off = (size_t)c * 1024 + chp * 32 + tg * 8 + chip * 4 + h8 * 2 + sel;
        g_rw[off] = __float2half(v);
    }
    for (int u = idx; u < 1024; u += stride)
        *(float4*)&g_bp[u << 2] = make_float4(bf[u], bi[u], bc[u], bo[u]);
    for (int i = idx; i < BB * 1024; i += stride)
        g_hp[0][i] = __float2half(0.0f);
}

// ===========================================================================
// Convert x -> single f16, layout [row=t*32+b][d]
// ===========================================================================
__global__ void conv_x_kernel(const float* __restrict__ x) {
    int idx = blockIdx.x * blockDim.x + threadIdx.x;
    int stride = gridDim.x * blockDim.x;
    const int N4 = BB * TT * DD / 4;
    for (int i = idx; i < N4; i += stride) {
        int d4 = i & 127;
        int rt = i >> 7;           // b*512 + t
        int b = rt >> 9, t = rt & 511;
        float4 v = *(const float4*)&x[(size_t)i * 4];
        size_t o = ((size_t)(t * 32 + b)) * 512 + d4 * 4;
        __half2 p0; p0.x = __float2half(v.x); p0.y = __float2half(v.y);
        __half2 p1; p1.x = __float2half(v.z); p1.y = __float2half(v.w);
        *(__half2*)(g_x + o) = p0;
        *(__half2*)(g_x + o + 2) = p1;
    }
}

// ===========================================================================
// zx GEMM via mma.sync, single-product f16:
//   zx[row][c] = bias[c] + x[row][:] . W[:][c]
// CTA tile 128(m) x 64(n), K chunks of 32. 8 warps (wm 0..3, wn 0..1),
// warp tile 32x32 = 2 m-frags x 4 n-frags.
// ===========================================================================
#define ZMT 128
#define ZNT 64
#define ZKC 32
#define ZST 40

__global__ __launch_bounds__(256) void zx_mma_kernel() {
    __shared__ __align__(16) __half sA[ZMT * ZST];
    __shared__ __align__(16) __half sB[ZNT * ZST];

    const int tid = threadIdx.x;
    const int lane = tid & 31;
    const int wid = tid >> 5;
    const int wm = wid >> 1;
    const int wn = wid & 1;
    const int gr = lane >> 2;
    const int tg = lane & 3;
    const int n0 = blockIdx.x * ZNT;
    const int row0 = blockIdx.y * ZMT;

    float c[2][4][4];
#pragma unroll
    for (int mi = 0; mi < 2; mi++)
#pragma unroll
        for (int ni = 0; ni < 4; ni++)
#pragma unroll
            for (int r = 0; r < 4; r++) c[mi][ni][r] = 0.0f;

    for (int kc = 0; kc < DD / ZKC; kc++) {
        __syncthreads();
        // stage A: 128 rows x 32 cols (2 tasks/thread)
#pragma unroll
        for (int it = 0; it < 2; it++) {
            int idx = tid + it * 256;
            int r = idx >> 2, q = idx & 3;
            size_t go = ((size_t)(row0 + r)) * 512 + kc * 32 + q * 8;
            *(uint4*)&sA[r * ZST + q * 8] = *(const uint4*)(g_x + go);
        }
        // stage B: 64 rows x 32 cols
        {
            int r = tid >> 2, q = tid & 3;
            size_t go = ((size_t)(n0 + r)) * 512 + kc * 32 + q * 8;
            *(uint4*)&sB[r * ZST + q * 8] = *(const uint4*)(g_bw + go);
        }
        __syncthreads();

#pragma unroll
        for (int ks = 0; ks < 2; ks++) {
            uint32_t a[2][4];
#pragma unroll
            for (int mi = 0; mi < 2; mi++) {
                int rb = (wm * 32 + mi * 16 + gr) * ZST + ks * 16 + tg * 2;
                a[mi][0] = *(const uint32_t*)&sA[rb];
                a[mi][1] = *(const uint32_t*)&sA[rb + 8 * ZST];
                a[mi][2] = *(const uint32_t*)&sA[rb + 8];
                a[mi][3] = *(const uint32_t*)&sA[rb + 8 * ZST + 8];
            }
            uint32_t b[4][2];
#pragma unroll
            for (int ni = 0; ni < 4; ni++) {
                int rb = (wn * 32 + ni * 8 + gr) * ZST + ks * 16 + tg * 2;
                b[ni][0] = *(const uint32_t*)&sB[rb];
                b[ni][1] = *(const uint32_t*)&sB[rb + 8];
            }
#pragma unroll
            for (int mi = 0; mi < 2; mi++)
#pragma unroll
                for (int ni = 0; ni < 4; ni++)
                    mma16816h(c[mi][ni], a[mi], b[ni]);
        }
    }

    const int rbase = row0 + wm * 32;
    const int cbase = n0 + wn * 32;
#pragma unroll
    for (int mi = 0; mi < 2; mi++) {
#pragma unroll
        for (int ni = 0; ni < 4; ni++) {
            int r = rbase + mi * 16 + gr;
            int col = cbase + ni * 8 + tg * 2;
            float2 b01 = *(const float2*)&g_bp[col];
            float2 v0 = make_float2(c[mi][ni][0] + b01.x, c[mi][ni][1] + b01.y);
            float2 v1 = make_float2(c[mi][ni][2] + b01.x, c[mi][ni][3] + b01.y);
            *(float2*)&g_zx[(size_t)r * NC + col] = v0;
            *(float2*)&g_zx[(size_t)(r + 8) * NC + col] = v1;
        }
    }
}

// ===========================================================================
// Persistent recurrent kernel — EXACT R15 (best measured: 2973us).
// Single-product f16: z = W_f16 . h_f16 (fp32 accum).
// smem: weights 32 x 2112B = 67584B + red[8][32][40] fp32 40960B = 108544B
// ===========================================================================
__global__ __launch_bounds__(256, 1) void lstm_persistent(float* __restrict__ out) {
    extern __shared__ __align__(16) char smem[];
    char* wsm = smem;                                   // packed weights
    float* red = (float*)(smem + 32 * WROWB);           // [8][32][40]

    const int tid = threadIdx.x;
    const int cu = blockIdx.x;
    const int lane = tid & 31;
    const int wid = tid >> 5;       // 0..7
    const int gr = lane >> 2;
    const int tg = lane & 3;
    const int cp0 = wid * 4;        // warp K-slice: chunk-pairs cp0..cp0+3 (K=128)

    // --- load resident packed weights ---
    for (int i = tid; i < 32 * 128; i += 256) {
        int lr = i >> 7, q = i & 127;
        *(uint4*)(wsm + lr * WROWB + q * 16) =
            *((const uint4*)(g_rw + (size_t)(cu * 32 + lr) * 1024) + q);
    }

    // --- gate-math roles ---
    const int up = tid >> 5;        // unit-in-CTA 0..7
    const int gb = tid & 31;        // batch 0..31
    const int ug = cu * 8 + up;     // global unit
    const int s_chp = ug >> 5;
    const int s_chip = (ug >> 4) & 1;
    const int s_ii = ug & 15;
    const int s_off = s_chp * 32 + ((s_ii & 6) >> 1) * 8 + s_chip * 4 + (s_ii >> 3) * 2 + (s_ii & 1);

    float c_state = 0.0f;
    __syncthreads();                // weights ready

    for (int t = 0; t < TT; t++) {
        const __half* __restrict__ hp = g_hp[t & 1];
        __half* __restrict__ hpo = g_hp[(t + 1) & 1];

        float4 zx4 = __ldcg((const float4*)&g_zx[((size_t)t * BB + gb) * NC + ug * 4]);

        float acc[2][4][4];
#pragma unroll
        for (int mi = 0; mi < 2; mi++)
#pragma unroll
            for (int ni = 0; ni < 4; ni++)
#pragma unroll
                for (int r = 0; r < 4; r++) acc[mi][ni][r] = 0.0f;

#define LDA(dst, chp) do { \
        (dst)[0] = __ldcg((const uint4*)(hp + (gr)      * 1024 + (chp) * 32) + tg); \
        (dst)[1] = __ldcg((const uint4*)(hp + (gr + 8)  * 1024 + (chp) * 32) + tg); \
        (dst)[2] = __ldcg((const uint4*)(hp + (gr + 16) * 1024 + (chp) * 32) + tg); \
        (dst)[3] = __ldcg((const uint4*)(hp + (gr + 24) * 1024 + (chp) * 32) + tg); \
    } while (0)

#define COMPUTE(buf, chp) do { \
        uint32_t a0c0[4] = {(buf)[0].x, (buf)[1].x, (buf)[0].y, (buf)[1].y}; \
        uint32_t a1c0[4] = {(buf)[2].x, (buf)[3].x, (buf)[2].y, (buf)[3].y}; \
        uint32_t a0c1[4] = {(buf)[0].z, (buf)[1].z, (buf)[0].w, (buf)[1].w}; \
        uint32_t a1c1[4] = {(buf)[2].z, (buf)[3].z, (buf)[2].w, (buf)[3].w}; \
        _Pragma("unroll") \
        for (int ni = 0; ni < 4; ni++) { \
            uint4 wb = *(const uint4*)(wsm + (ni * 8 + gr) * WROWB + (chp) * 64 + tg * 16); \
            uint32_t b0[2] = {wb.x, wb.y}; \
            uint32_t b1[2] = {wb.z, wb.w}; \
            mma16816h(acc[0][ni], a0c0, b0); \
            mma16816h(acc[1][ni], a1c0, b0); \
            mma16816h(acc[0][ni], a0c1, b1); \
            mma16816h(acc[1][ni], a1c1, b1); \
        } \
    } while (0)

        uint4 cur[4], nxt[4];
        LDA(cur, cp0);
#pragma unroll
        for (int i = 0; i < 4; i += 2) {
            LDA(nxt, cp0 + i + 1);
            COMPUTE(cur, cp0 + i);
            if (i + 2 < 4) LDA(cur, cp0 + i + 2);
            COMPUTE(nxt, cp0 + i + 1);
        }

        // ---- write partials: red[wid][b][40] ----
#pragma unroll
        for (int mi = 0; mi < 2; mi++)
#pragma unroll
            for (int ni = 0; ni < 4; ni++) {
                float* b0 = &red[((size_t)wid * 32 + mi * 16 + gr) * 40 + ni * 8 + tg * 2];
                *(float2*)b0 = make_float2(acc[mi][ni][0], acc[mi][ni][1]);
                *(float2*)(b0 + 8 * 40) = make_float2(acc[mi][ni][2], acc[mi][ni][3]);
            }
        __syncthreads();

        // ---- reduce + gate math: thread = (unit up, batch gb) ----
        float h_new;
        {
            float4 z = make_float4(0.f, 0.f, 0.f, 0.f);
#pragma unroll
            for (int s = 0; s < NWARP; s++) {
                float4 v = *(const float4*)&red[((size_t)s * 32 + gb) * 40 + up * 4];
                z.x += v.x; z.y += v.y; z.z += v.z; z.w += v.w;
            }
            float zf = z.x + zx4.x;
            float zi = z.y + zx4.y;
            float zg = z.z + zx4.z;
            float zo = z.w + zx4.w;

            float f = sigmoidf_(zf);
            float ii = sigmoidf_(zi);
            float g = tanhf_(zg);
            float o = sigmoidf_(zo);
            c_state = f * c_state + ii * g;
            h_new = o * tanhf_(c_state);

            hpo[gb * 1024 + s_off] = __float2half(h_new);
        }

        // ---- grid barrier (release/acquire) ----
        __syncthreads();   // h stores issued, red consumed
        if (tid == 0) bar_arrive_release(&g_bar);

        out[((size_t)gb * TT + t) * UU + ug] = h_new;

        if (tid == 0) {
            unsigned target = (unsigned)NCTA * (unsigned)(t + 1);
            while (ld_acquire(&g_bar) < target) {}
        }
        __syncthreads();
    }
#undef LDA
#undef COMPUTE
}

// ===========================================================================
// Launch
// ===========================================================================
extern "C" void kernel_launch(void* const* d_in, const int* in_sizes, int n_in,
                              void* d_out, int out_size) {
    const float* data = (const float*)d_in[0];
    const float* Wf = (const float*)d_in[1];
    const float* bf = (const float*)d_in[2];
    const float* Wi = (const float*)d_in[3];
    const float* bi = (const float*)d_in[4];
    const float* Wc = (const float*)d_in[5];
    const float* bc = (const float*)d_in[6];
    const float* Wo = (const float*)d_in[7];
    const float* bo = (const float*)d_in[8];
    float* out = (float*)d_out;

    static int attr_set = 0;
    const int psmem_bytes = 32 * WROWB + NWARP * 32 * 40 * 4;  // 108544
    if (!attr_set) {
        cudaFuncSetAttribute(lstm_persistent,
                             cudaFuncAttributeMaxDynamicSharedMemorySize, psmem_bytes);
        attr_set = 1;
    }

    prep_kernel<<<512, 256>>>(Wf, Wi, Wc, Wo, bf, bi, bc, bo);
    conv_x_kernel<<<2048, 256>>>(data);

    dim3 zgrid(NC / ZNT, (TT * BB) / ZMT);  // (64, 128)
    zx_mma_kernel<<<zgrid, 256>>>();

    lstm_persistent<<<NCTA, 256, psmem_bytes>>>(out);
}